// round 8
// baseline (speedup 1.0000x reference)
#include <cuda_runtime.h>
#include <math.h>
#include <stdint.h>

// Problem shape (fixed for this dataset instance)
constexpr int Bb = 4;
constexpr int Tt = 4096;
constexpr int Dd = 2048;
constexpr int BT = Bb * Tt;           // 16384 rows
constexpr float EPS = 1e-5f;

// Scan chunking
constexpr int NC = 32;
constexpr int CH = Tt / NC;           // 128

// GEMM tiling (mma.sync tf32): CTA 128x256, 512 threads, BK=16, 4 stages
constexpr int BM = 128;
constexpr int BN = 256;
constexpr int BK = 16;
constexpr int LDA_S = 20;             // padded floats per A row (bank-clean)
constexpr int LDB_S = 264;            // padded floats per B row (bank-clean)
constexpr int STAGES = 4;
constexpr int A_FLOATS = BM * LDA_S;  // 2560
constexpr int B_FLOATS = BK * LDB_S;  // 4224
constexpr int STG_FLOATS = A_FLOATS + B_FLOATS;       // 6784
constexpr int GEMM_SMEM = STAGES * STG_FLOATS * 4;    // 108544 bytes

// Scratch (device globals — no allocation allowed)
__device__ float g_a   [(size_t)BT * Dd];      // sigmoid(f)
__device__ float g_si  [(size_t)BT * Dd];      // silu(i)
__device__ float g_gg  [(size_t)BT * Dd];      // silu(g)
__device__ float g_o   [(size_t)BT * Dd];
__device__ float g_u   [(size_t)BT * Dd];
__device__ float g_xr  [(size_t)BT * Dd];      // tf32-rounded x
__device__ float g_wr  [(size_t)4 * Dd * Dd];  // tf32-rounded weights [K][N]
__device__ float g_cA  [(size_t)Bb * NC * Dd];
__device__ float g_cH  [(size_t)Bb * NC * Dd];
__device__ float g_cIn [(size_t)Bb * NC * Dd];

// ---------------------------------------------------------------------------
__device__ __forceinline__ float tf32r(float x) {
    uint32_t u;
    asm("cvt.rna.tf32.f32 %0, %1;" : "=r"(u) : "f"(x));
    return __uint_as_float(u);
}

__device__ __forceinline__ void cp16(uint32_t dst, const void* src) {
    asm volatile("cp.async.cg.shared.global [%0], [%1], 16;\n" :: "r"(dst), "l"(src));
}

__device__ __forceinline__ void mma1688(float* d, const uint32_t* a, const uint32_t* b) {
    asm volatile(
        "mma.sync.aligned.m16n8k8.row.col.f32.tf32.tf32.f32 "
        "{%0,%1,%2,%3}, {%4,%5,%6,%7}, {%8,%9}, {%0,%1,%2,%3};"
        : "+f"(d[0]), "+f"(d[1]), "+f"(d[2]), "+f"(d[3])
        : "r"(a[0]), "r"(a[1]), "r"(a[2]), "r"(a[3]), "r"(b[0]), "r"(b[1]));
}

__device__ __forceinline__ float sigm(float v) { return 1.0f / (1.0f + __expf(-v)); }

// ---------------------------------------------------------------------------
__global__ void round_tf32_kernel(const float* __restrict__ in,
                                  float* __restrict__ out, int n4)
{
    int i = blockIdx.x * blockDim.x + threadIdx.x;
    if (i < n4) {
        float4 v = reinterpret_cast<const float4*>(in)[i];
        v.x = tf32r(v.x); v.y = tf32r(v.y); v.z = tf32r(v.z); v.w = tf32r(v.w);
        reinterpret_cast<float4*>(out)[i] = v;
    }
}

// ---------------------------------------------------------------------------
// C[M,N] = act(A[M,K] * B[K,N]); A row-major K-contig, B row-major N-contig.
// mode: 0 = identity, 1 = sigmoid, 2 = silu.
// CTA 128x256, 512 threads (16 warps: 4m x 4n, warp 32x64).
// BK=16, 4-stage cp.async ring, load-after-compute.
// ---------------------------------------------------------------------------
__global__ __launch_bounds__(512, 1)
void gemm_mma(const float* __restrict__ A, const float* __restrict__ Bw,
              float* __restrict__ C, int M, int N, int K, int mode)
{
    extern __shared__ float smem[];

    const int tid  = threadIdx.x;
    const int warp = tid >> 5;
    const int lane = tid & 31;
    const int wm   = warp >> 2;          // 0..3
    const int wn   = warp & 3;           // 0..3
    const int gid  = lane >> 2;          // 0..7
    const int tig  = lane & 3;           // 0..3
    const int m0   = blockIdx.y * BM;
    const int n0   = blockIdx.x * BN;

    float acc[2][8][4];                  // warp tile 32(m) x 64(n)
#pragma unroll
    for (int i = 0; i < 2; i++)
#pragma unroll
        for (int j = 0; j < 8; j++)
#pragma unroll
            for (int r = 0; r < 4; r++)
                acc[i][j][r] = 0.0f;

    const uint32_t smem_b = (uint32_t)__cvta_generic_to_shared(smem);

    auto load_stage = [&](int kt, int s) {
        const int k0 = kt * BK;
        const uint32_t sa = smem_b + s * STG_FLOATS * 4;
        const uint32_t sb = sa + A_FLOATS * 4;
        // A: 128 rows x 4 float4 = 512 -> 1 per thread
        {
            int r = tid >> 2, c4 = tid & 3;
            cp16(sa + (r * LDA_S + c4 * 4) * 4,
                 A + (size_t)(m0 + r) * K + k0 + c4 * 4);
        }
        // B: 16 rows x 64 float4 = 1024 -> 2 per thread
#pragma unroll
        for (int i = 0; i < 2; i++) {
            int e = tid + i * 512;
            int r = e >> 6, c4 = e & 63;
            cp16(sb + (r * LDB_S + c4 * 4) * 4,
                 Bw + (size_t)(k0 + r) * N + n0 + c4 * 4);
        }
        asm volatile("cp.async.commit_group;\n" ::: "memory");
    };

    const int KT = K / BK;               // 128
    load_stage(0, 0);
    load_stage(1, 1);
    load_stage(2, 2);

    for (int kt = 0; kt < KT; kt++) {
        const int s = kt & 3;
        if (kt < KT - 2)
            asm volatile("cp.async.wait_group 2;\n" ::: "memory");
        else if (kt == KT - 2)
            asm volatile("cp.async.wait_group 1;\n" ::: "memory");
        else
            asm volatile("cp.async.wait_group 0;\n" ::: "memory");
        __syncthreads();

        const float* sA = smem + s * STG_FLOATS;
        const float* sB = sA + A_FLOATS;

#pragma unroll
        for (int kk = 0; kk < 2; kk++) {             // two k8 steps
            uint32_t af[2][4];
            uint32_t bf[8][2];
#pragma unroll
            for (int im = 0; im < 2; im++) {
                int r0 = wm * 32 + im * 16 + gid;
                int c0 = kk * 8 + tig;
                af[im][0] = __float_as_uint(sA[r0 * LDA_S + c0]);
                af[im][1] = __float_as_uint(sA[(r0 + 8) * LDA_S + c0]);
                af[im][2] = __float_as_uint(sA[r0 * LDA_S + c0 + 4]);
                af[im][3] = __float_as_uint(sA[(r0 + 8) * LDA_S + c0 + 4]);
            }
#pragma unroll
            for (int in = 0; in < 8; in++) {
                int n = wn * 64 + in * 8 + gid;
                int k = kk * 8 + tig;
                bf[in][0] = __float_as_uint(sB[k * LDB_S + n]);
                bf[in][1] = __float_as_uint(sB[(k + 4) * LDB_S + n]);
            }
#pragma unroll
            for (int im = 0; im < 2; im++)
#pragma unroll
                for (int in = 0; in < 8; in++)
                    mma1688(acc[im][in], af[im], bf[in]);
        }

        // Issue next load AFTER compute (proven ordering)
        if (kt + 3 < KT)
            load_stage(kt + 3, (kt + 3) & 3);
    }

    // Epilogue with fused activation
#pragma unroll
    for (int im = 0; im < 2; im++) {
        int row0 = m0 + wm * 32 + im * 16 + gid;
#pragma unroll
        for (int in = 0; in < 8; in++) {
            int col = n0 + wn * 64 + in * 8 + 2 * tig;
#pragma unroll
            for (int h = 0; h < 2; h++) {
                float v0 = acc[im][in][2 * h], v1 = acc[im][in][2 * h + 1];
                if (mode == 1)      { v0 = sigm(v0);  v1 = sigm(v1); }
                else if (mode == 2) { v0 *= sigm(v0); v1 *= sigm(v1); }
                *reinterpret_cast<float2*>(
                    &C[(size_t)(row0 + 8 * h) * N + col]) = make_float2(v0, v1);
            }
        }
    }
}

// ---------------------------------------------------------------------------
// Parallel scan (3 passes), pure FMA: h_t = a*h + si*(1-a)
// ---------------------------------------------------------------------------
__global__ void scan_pass1(const float* __restrict__ aA,
                           const float* __restrict__ siA,
                           float* __restrict__ o,
                           float* __restrict__ cA,
                           float* __restrict__ cH)
{
    const int blocksPerBC = Dd / 256;            // 8
    int d  = (blockIdx.x % blocksPerBC) * 256 + threadIdx.x;
    int bc = blockIdx.x / blocksPerBC;
    int b  = bc / NC;
    int c  = bc % NC;
    size_t base = ((size_t)b * Tt + (size_t)c * CH) * Dd + d;

    float h = 0.0f, pa = 1.0f;
#pragma unroll 4
    for (int t = 0; t < CH; t++) {
        size_t idx = base + (size_t)t * Dd;
        float a  = aA[idx];
        float in = siA[idx] * (1.0f - a);
        h  = fmaf(a, h, in);
        pa *= a;
        o[idx] = h;
    }
    cA[(size_t)bc * Dd + d] = pa;
    cH[(size_t)bc * Dd + d] = h;
}

__global__ void scan_pass2(const float* __restrict__ cA,
                           const float* __restrict__ cH,
                           float* __restrict__ cIn)
{
    int ch = blockIdx.x * blockDim.x + threadIdx.x;
    int b  = ch / Dd;
    int d  = ch - b * Dd;
    float H = 0.0f;
#pragma unroll
    for (int c = 0; c < NC; c++) {
        size_t idx = ((size_t)b * NC + c) * Dd + d;
        cIn[idx] = H;
        H = fmaf(cA[idx], H, cH[idx]);
    }
}

__global__ void scan_pass3(const float* __restrict__ aA,
                           const float* __restrict__ cIn,
                           float* __restrict__ o)
{
    const int blocksPerBC = Dd / 256;
    int d  = (blockIdx.x % blocksPerBC) * 256 + threadIdx.x;
    int bc = blockIdx.x / blocksPerBC;
    int b  = bc / NC;
    int c  = bc % NC;
    if (c == 0) return;

    float pa = cIn[(size_t)bc * Dd + d];
    size_t base = ((size_t)b * Tt + (size_t)c * CH) * Dd + d;
#pragma unroll 4
    for (int t = 0; t < CH; t++) {
        size_t idx = base + (size_t)t * Dd;
        pa *= aA[idx];
        o[idx] += pa;
    }
}

// ---------------------------------------------------------------------------
// u = tf32_round( RMSNorm(o) * w * gsw ), gsw = silu(g) precomputed
// ---------------------------------------------------------------------------
__global__ __launch_bounds__(256)
void norm_gate_kernel(const float* __restrict__ o,
                      const float* __restrict__ gsw,
                      const float* __restrict__ w,
                      float* __restrict__ u)
{
    int row = blockIdx.x;
    const float4* op = reinterpret_cast<const float4*>(o + (size_t)row * Dd);
    const float4* gp = reinterpret_cast<const float4*>(gsw + (size_t)row * Dd);
    const float4* wp = reinterpret_cast<const float4*>(w);
    float4*       up = reinterpret_cast<float4*>(u + (size_t)row * Dd);

    float4 va[2];
    float s = 0.0f;
#pragma unroll
    for (int i = 0; i < 2; i++) {
        va[i] = op[threadIdx.x + i * 256];
        s += va[i].x * va[i].x + va[i].y * va[i].y
           + va[i].z * va[i].z + va[i].w * va[i].w;
    }
#pragma unroll
    for (int k = 16; k > 0; k >>= 1)
        s += __shfl_xor_sync(0xffffffffu, s, k);
    __shared__ float red[8];
    if ((threadIdx.x & 31) == 0) red[threadIdx.x >> 5] = s;
    __syncthreads();
    if (threadIdx.x < 8) {
        float v = red[threadIdx.x];
#pragma unroll
        for (int k = 4; k > 0; k >>= 1)
            v += __shfl_xor_sync(0xffu, v, k);
        if (threadIdx.x == 0) red[0] = v;
    }
    __syncthreads();
    float r = rsqrtf(red[0] * (1.0f / Dd) + EPS);

#pragma unroll
    for (int i = 0; i < 2; i++) {
        float4 vg = gp[threadIdx.x + i * 256];
        float4 vw = wp[threadIdx.x + i * 256];
        float4 out;
        out.x = tf32r(va[i].x * r * vw.x * vg.x);
        out.y = tf32r(va[i].y * r * vw.y * vg.y);
        out.z = tf32r(va[i].z * r * vw.z * vg.z);
        out.w = tf32r(va[i].w * r * vw.w * vg.w);
        up[threadIdx.x + i * 256] = out;
    }
}

// ---------------------------------------------------------------------------
extern "C" void kernel_launch(void* const* d_in, const int* in_sizes, int n_in,
                              void* d_out, int out_size)
{
    const float* x  = (const float*)d_in[0];
    const float* Wi = (const float*)d_in[1];
    const float* Wf = (const float*)d_in[2];
    const float* Wg = (const float*)d_in[3];
    const float* Wo = (const float*)d_in[4];
    const float* gw = (const float*)d_in[5];
    float* out = (float*)d_out;

    float *aA, *siA, *gg, *o, *u, *xr, *wr, *cA, *cH, *cIn;
    cudaGetSymbolAddress((void**)&aA,  g_a);
    cudaGetSymbolAddress((void**)&siA, g_si);
    cudaGetSymbolAddress((void**)&gg,  g_gg);
    cudaGetSymbolAddress((void**)&o,   g_o);
    cudaGetSymbolAddress((void**)&u,   g_u);
    cudaGetSymbolAddress((void**)&xr,  g_xr);
    cudaGetSymbolAddress((void**)&wr,  g_wr);
    cudaGetSymbolAddress((void**)&cA,  g_cA);
    cudaGetSymbolAddress((void**)&cH,  g_cH);
    cudaGetSymbolAddress((void**)&cIn, g_cIn);

    cudaFuncSetAttribute(gemm_mma,
                         cudaFuncAttributeMaxDynamicSharedMemorySize, GEMM_SMEM);

    const size_t WSZ = (size_t)Dd * Dd;

    // Pre-round x and weights to tf32 (weights stay in native [K][N] layout)
    {
        int n4x = (int)((size_t)BT * Dd / 4);
        int n4w = (int)(WSZ / 4);
        round_tf32_kernel<<<n4x / 256, 256>>>(x,  xr, n4x);
        round_tf32_kernel<<<n4w / 256, 256>>>(Wi, wr + 0 * WSZ, n4w);
        round_tf32_kernel<<<n4w / 256, 256>>>(Wf, wr + 1 * WSZ, n4w);
        round_tf32_kernel<<<n4w / 256, 256>>>(Wg, wr + 2 * WSZ, n4w);
        round_tf32_kernel<<<n4w / 256, 256>>>(Wo, wr + 3 * WSZ, n4w);
    }

    dim3 ggrid(Dd / BN, BT / BM);   // (8, 128)
    dim3 gblk(512);

    // i: silu(i); f: sigmoid(f); g: silu(g)
    gemm_mma<<<ggrid, gblk, GEMM_SMEM>>>(xr, wr + 0 * WSZ, siA, BT, Dd, Dd, 2);
    gemm_mma<<<ggrid, gblk, GEMM_SMEM>>>(xr, wr + 1 * WSZ, aA,  BT, Dd, Dd, 1);
    gemm_mma<<<ggrid, gblk, GEMM_SMEM>>>(xr, wr + 2 * WSZ, gg,  BT, Dd, Dd, 2);

    const int scanBlocks = Bb * NC * (Dd / 256);   // 1024
    scan_pass1<<<scanBlocks, 256>>>(aA, siA, o, cA, cH);
    scan_pass2<<<(Bb * Dd) / 256, 256>>>(cA, cH, cIn);
    scan_pass3<<<scanBlocks, 256>>>(aA, cIn, o);

    norm_gate_kernel<<<BT, 256>>>(o, gg, gw, u);

    // Output GEMM (identity epilogue)
    gemm_mma<<<ggrid, gblk, GEMM_SMEM>>>(u, wr + 3 * WSZ, out, BT, Dd, Dd, 0);
}

// round 10
// speedup vs baseline: 1.9965x; 1.9965x over previous
#include <cuda_runtime.h>
#include <cuda_fp16.h>
#include <math.h>
#include <stdint.h>

// Problem shape (fixed for this dataset instance)
constexpr int Bb = 4;
constexpr int Tt = 4096;
constexpr int Dd = 2048;
constexpr int BT = Bb * Tt;           // 16384 rows
constexpr float EPS = 1e-5f;

// Scan chunking
constexpr int NC = 32;
constexpr int CH = Tt / NC;           // 128

// GEMM tiling (mma.sync f16 m16n8k16): CTA 128x128, BK=32, 4 stages, 2 CTAs/SM
constexpr int BM = 128;
constexpr int BN = 128;
constexpr int BK = 32;                // 2 x k16 per stage
constexpr int LDA_W = 20;             // A row length in half2 words (16 data + 4 pad)
constexpr int LDB_W = 136;            // B row length in words (128 data + 8 pad)
constexpr int STAGES = 4;
constexpr int A_WORDS = BM * LDA_W;   // 2560
constexpr int B_WORDS = (BK / 2) * LDB_W;             // 16*136 = 2176
constexpr int STG_WORDS = A_WORDS + B_WORDS;          // 4736
constexpr int GEMM_SMEM = STAGES * STG_WORDS * 4;     // 75776 bytes

// Scratch (device globals — no allocation allowed)
__device__ float  g_a   [(size_t)BT * Dd];     // sigmoid(f)
__device__ float  g_si  [(size_t)BT * Dd];     // silu(i)
__device__ float  g_gg  [(size_t)BT * Dd];     // silu(g)
__device__ float  g_o   [(size_t)BT * Dd];
__device__ __half g_uh  [(size_t)BT * Dd];     // fp16 u (input to output GEMM)
__device__ __half g_xh  [(size_t)BT * Dd];     // fp16 x
__device__ __half g_wh  [(size_t)4 * Dd * Dd]; // fp16 weights, k-pair interleaved [K/2][N]
__device__ float  g_cA  [(size_t)Bb * NC * Dd];
__device__ float  g_cH  [(size_t)Bb * NC * Dd];
__device__ float  g_cIn [(size_t)Bb * NC * Dd];

// ---------------------------------------------------------------------------
__device__ __forceinline__ void cp16(uint32_t dst, const void* src) {
    asm volatile("cp.async.cg.shared.global [%0], [%1], 16;\n" :: "r"(dst), "l"(src));
}

__device__ __forceinline__ void mma16816(float* d, const uint32_t* a, const uint32_t* b) {
    asm volatile(
        "mma.sync.aligned.m16n8k16.row.col.f32.f16.f16.f32 "
        "{%0,%1,%2,%3}, {%4,%5,%6,%7}, {%8,%9}, {%0,%1,%2,%3};"
        : "+f"(d[0]), "+f"(d[1]), "+f"(d[2]), "+f"(d[3])
        : "r"(a[0]), "r"(a[1]), "r"(a[2]), "r"(a[3]), "r"(b[0]), "r"(b[1]));
}

__device__ __forceinline__ float sigm(float v) { return 1.0f / (1.0f + __expf(-v)); }

// ---------------------------------------------------------------------------
// x: float -> half, contiguous
__global__ void f2h_kernel(const float* __restrict__ in,
                           __half* __restrict__ out, int n4)
{
    int i = blockIdx.x * blockDim.x + threadIdx.x;
    if (i < n4) {
        float4 v = reinterpret_cast<const float4*>(in)[i];
        __half2 h0 = __floats2half2_rn(v.x, v.y);
        __half2 h1 = __floats2half2_rn(v.z, v.w);
        uint2 p;
        p.x = *reinterpret_cast<uint32_t*>(&h0);
        p.y = *reinterpret_cast<uint32_t*>(&h1);
        reinterpret_cast<uint2*>(out)[i] = p;
    }
}

// Weight: [K][N] float -> [K/2][N] half2 words: out2[k2][n] = (W[2k2][n], W[2k2+1][n])
__global__ void wint_kernel(const float* __restrict__ W, __half* __restrict__ out)
{
    int n4 = blockIdx.x * blockDim.x + threadIdx.x;    // 0..Dd/4-1
    int k2 = blockIdx.y;                               // 0..Dd/2-1
    float4 r0 = *reinterpret_cast<const float4*>(&W[(size_t)(2 * k2) * Dd + n4 * 4]);
    float4 r1 = *reinterpret_cast<const float4*>(&W[(size_t)(2 * k2 + 1) * Dd + n4 * 4]);
    __half2 h0 = __floats2half2_rn(r0.x, r1.x);
    __half2 h1 = __floats2half2_rn(r0.y, r1.y);
    __half2 h2 = __floats2half2_rn(r0.z, r1.z);
    __half2 h3 = __floats2half2_rn(r0.w, r1.w);
    uint4 p;
    p.x = *reinterpret_cast<uint32_t*>(&h0);
    p.y = *reinterpret_cast<uint32_t*>(&h1);
    p.z = *reinterpret_cast<uint32_t*>(&h2);
    p.w = *reinterpret_cast<uint32_t*>(&h3);
    *reinterpret_cast<uint4*>(
        reinterpret_cast<__half2*>(out) + (size_t)k2 * Dd + n4 * 4) = p;
}

// ---------------------------------------------------------------------------
// C[M,N] = act(A[M,K] * B[K,N]); A half row-major K-contig; Bw2 half2-interleaved
// [K/2][N]. mode: 0 = identity, 1 = sigmoid, 2 = silu. fp32 accumulate.
// Round-4 pipeline: 4-stage cp.async, load-after-compute, 2 CTAs/SM.
// ---------------------------------------------------------------------------
__global__ __launch_bounds__(256, 2)
void gemm_f16(const __half* __restrict__ A, const __half* __restrict__ Bw2,
              float* __restrict__ C, int M, int N, int K, int mode)
{
    extern __shared__ uint32_t smem[];

    const int tid  = threadIdx.x;
    const int warp = tid >> 5;
    const int lane = tid & 31;
    const int wm   = warp >> 2;          // 0..1
    const int wn   = warp & 3;           // 0..3
    const int gid  = lane >> 2;          // 0..7
    const int tig  = lane & 3;           // 0..3
    const int m0   = blockIdx.y * BM;
    const int n0   = blockIdx.x * BN;

    float acc[4][4][4];
#pragma unroll
    for (int i = 0; i < 4; i++)
#pragma unroll
        for (int j = 0; j < 4; j++)
#pragma unroll
            for (int r = 0; r < 4; r++)
                acc[i][j][r] = 0.0f;

    const uint32_t smem_b = (uint32_t)__cvta_generic_to_shared(smem);

    auto load_stage = [&](int kt, int s) {
        const int k0  = kt * BK;           // half index
        const int k20 = kt * (BK / 2);     // word row in interleaved weights
        const uint32_t sa = smem_b + s * STG_WORDS * 4;
        const uint32_t sb = sa + A_WORDS * 4;
        // A: 128 rows x 32 halves = 4 x 16B chunks per row -> 512 chunks, 2/thread
#pragma unroll
        for (int i = 0; i < 2; i++) {
            int e = tid + i * 256;
            int r = e >> 2, c4 = e & 3;
            cp16(sa + (r * LDA_W + c4 * 4) * 4,
                 A + (size_t)(m0 + r) * K + k0 + c4 * 8);
        }
        // B: 16 word-rows x 128 words = 32 x 16B chunks per row -> 512, 2/thread
#pragma unroll
        for (int i = 0; i < 2; i++) {
            int e = tid + i * 256;
            int r = e >> 5, c4 = e & 31;
            cp16(sb + (r * LDB_W + c4 * 4) * 4,
                 Bw2 + 2 * ((size_t)(k20 + r) * N + n0 + c4 * 4));
        }
        asm volatile("cp.async.commit_group;\n" ::: "memory");
    };

    const int KT = K / BK;               // 64
    load_stage(0, 0);
    load_stage(1, 1);
    load_stage(2, 2);

    for (int kt = 0; kt < KT; kt++) {
        const int s = kt & 3;
        if (kt < KT - 2)
            asm volatile("cp.async.wait_group 2;\n" ::: "memory");
        else if (kt == KT - 2)
            asm volatile("cp.async.wait_group 1;\n" ::: "memory");
        else
            asm volatile("cp.async.wait_group 0;\n" ::: "memory");
        __syncthreads();

        const uint32_t* sA = smem + s * STG_WORDS;
        const uint32_t* sB = sA + A_WORDS;

#pragma unroll
        for (int kk = 0; kk < 2; kk++) {             // two k16 steps
            uint32_t af[4][4];
            uint32_t bf[4][2];
            const int c0 = kk * 8 + tig;             // A word col
#pragma unroll
            for (int im = 0; im < 4; im++) {
                int r0 = wm * 64 + im * 16 + gid;
                af[im][0] = sA[r0 * LDA_W + c0];
                af[im][1] = sA[(r0 + 8) * LDA_W + c0];
                af[im][2] = sA[r0 * LDA_W + c0 + 4];
                af[im][3] = sA[(r0 + 8) * LDA_W + c0 + 4];
            }
#pragma unroll
            for (int in = 0; in < 4; in++) {
                int n = wn * 32 + in * 8 + gid;
                bf[in][0] = sB[(kk * 8 + tig) * LDB_W + n];
                bf[in][1] = sB[(kk * 8 + tig + 4) * LDB_W + n];
            }
#pragma unroll
            for (int im = 0; im < 4; im++)
#pragma unroll
                for (int in = 0; in < 4; in++)
                    mma16816(acc[im][in], af[im], bf[in]);
        }

        // Issue next load AFTER compute (proven ordering)
        if (kt + 3 < KT)
            load_stage(kt + 3, (kt + 3) & 3);
    }

    // Epilogue with fused activation (same fragment layout as m16n8k8)
#pragma unroll
    for (int im = 0; im < 4; im++) {
        int row0 = m0 + wm * 64 + im * 16 + gid;
#pragma unroll
        for (int in = 0; in < 4; in++) {
            int col = n0 + wn * 32 + in * 8 + 2 * tig;
#pragma unroll
            for (int h = 0; h < 2; h++) {
                float v0 = acc[im][in][2 * h], v1 = acc[im][in][2 * h + 1];
                if (mode == 1)      { v0 = sigm(v0);  v1 = sigm(v1); }
                else if (mode == 2) { v0 *= sigm(v0); v1 *= sigm(v1); }
                *reinterpret_cast<float2*>(
                    &C[(size_t)(row0 + 8 * h) * N + col]) = make_float2(v0, v1);
            }
        }
    }
}

// ---------------------------------------------------------------------------
// Parallel scan (3 passes), pure FMA: h_t = a*h + si*(1-a)
// ---------------------------------------------------------------------------
__global__ void scan_pass1(const float* __restrict__ aA,
                           const float* __restrict__ siA,
                           float* __restrict__ o,
                           float* __restrict__ cA,
                           float* __restrict__ cH)
{
    const int blocksPerBC = Dd / 256;            // 8
    int d  = (blockIdx.x % blocksPerBC) * 256 + threadIdx.x;
    int bc = blockIdx.x / blocksPerBC;
    int b  = bc / NC;
    int c  = bc % NC;
    size_t base = ((size_t)b * Tt + (size_t)c * CH) * Dd + d;

    float h = 0.0f, pa = 1.0f;
#pragma unroll 4
    for (int t = 0; t < CH; t++) {
        size_t idx = base + (size_t)t * Dd;
        float a  = aA[idx];
        float in = siA[idx] * (1.0f - a);
        h  = fmaf(a, h, in);
        pa *= a;
        o[idx] = h;
    }
    cA[(size_t)bc * Dd + d] = pa;
    cH[(size_t)bc * Dd + d] = h;
}

__global__ void scan_pass2(const float* __restrict__ cA,
                           const float* __restrict__ cH,
                           float* __restrict__ cIn)
{
    int ch = blockIdx.x * blockDim.x + threadIdx.x;
    int b  = ch / Dd;
    int d  = ch - b * Dd;
    float H = 0.0f;
#pragma unroll
    for (int c = 0; c < NC; c++) {
        size_t idx = ((size_t)b * NC + c) * Dd + d;
        cIn[idx] = H;
        H = fmaf(cA[idx], H, cH[idx]);
    }
}

__global__ void scan_pass3(const float* __restrict__ aA,
                           const float* __restrict__ cIn,
                           float* __restrict__ o)
{
    const int blocksPerBC = Dd / 256;
    int d  = (blockIdx.x % blocksPerBC) * 256 + threadIdx.x;
    int bc = blockIdx.x / blocksPerBC;
    int b  = bc / NC;
    int c  = bc % NC;
    if (c == 0) return;

    float pa = cIn[(size_t)bc * Dd + d];
    size_t base = ((size_t)b * Tt + (size_t)c * CH) * Dd + d;
#pragma unroll 4
    for (int t = 0; t < CH; t++) {
        size_t idx = base + (size_t)t * Dd;
        pa *= aA[idx];
        o[idx] += pa;
    }
}

// ---------------------------------------------------------------------------
// u = half( RMSNorm(o) * w * gsw ), gsw = silu(g) precomputed
// ---------------------------------------------------------------------------
__global__ __launch_bounds__(256)
void norm_gate_kernel(const float* __restrict__ o,
                      const float* __restrict__ gsw,
                      const float* __restrict__ w,
                      __half* __restrict__ u)
{
    int row = blockIdx.x;
    const float4* op = reinterpret_cast<const float4*>(o + (size_t)row * Dd);
    const float4* gp = reinterpret_cast<const float4*>(gsw + (size_t)row * Dd);
    const float4* wp = reinterpret_cast<const float4*>(w);
    uint2*        up = reinterpret_cast<uint2*>(u + (size_t)row * Dd);

    float4 va[2];
    float s = 0.0f;
#pragma unroll
    for (int i = 0; i < 2; i++) {
        va[i] = op[threadIdx.x + i * 256];
        s += va[i].x * va[i].x + va[i].y * va[i].y
           + va[i].z * va[i].z + va[i].w * va[i].w;
    }
#pragma unroll
    for (int k = 16; k > 0; k >>= 1)
        s += __shfl_xor_sync(0xffffffffu, s, k);
    __shared__ float red[8];
    if ((threadIdx.x & 31) == 0) red[threadIdx.x >> 5] = s;
    __syncthreads();
    if (threadIdx.x < 8) {
        float v = red[threadIdx.x];
#pragma unroll
        for (int k = 4; k > 0; k >>= 1)
            v += __shfl_xor_sync(0xffu, v, k);
        if (threadIdx.x == 0) red[0] = v;
    }
    __syncthreads();
    float r = rsqrtf(red[0] * (1.0f / Dd) + EPS);

#pragma unroll
    for (int i = 0; i < 2; i++) {
        float4 vg = gp[threadIdx.x + i * 256];
        float4 vw = wp[threadIdx.x + i * 256];
        __half2 h0 = __floats2half2_rn(va[i].x * r * vw.x * vg.x,
                                       va[i].y * r * vw.y * vg.y);
        __half2 h1 = __floats2half2_rn(va[i].z * r * vw.z * vg.z,
                                       va[i].w * r * vw.w * vg.w);
        uint2 p;
        p.x = *reinterpret_cast<uint32_t*>(&h0);
        p.y = *reinterpret_cast<uint32_t*>(&h1);
        up[threadIdx.x + i * 256] = p;
    }
}

// ---------------------------------------------------------------------------
extern "C" void kernel_launch(void* const* d_in, const int* in_sizes, int n_in,
                              void* d_out, int out_size)
{
    const float* x  = (const float*)d_in[0];
    const float* Wi = (const float*)d_in[1];
    const float* Wf = (const float*)d_in[2];
    const float* Wg = (const float*)d_in[3];
    const float* Wo = (const float*)d_in[4];
    const float* gw = (const float*)d_in[5];
    float* out = (float*)d_out;

    float *aA, *siA, *gg, *o, *cA, *cH, *cIn;
    __half *uh, *xh, *wh;
    cudaGetSymbolAddress((void**)&aA,  g_a);
    cudaGetSymbolAddress((void**)&siA, g_si);
    cudaGetSymbolAddress((void**)&gg,  g_gg);
    cudaGetSymbolAddress((void**)&o,   g_o);
    cudaGetSymbolAddress((void**)&uh,  g_uh);
    cudaGetSymbolAddress((void**)&xh,  g_xh);
    cudaGetSymbolAddress((void**)&wh,  g_wh);
    cudaGetSymbolAddress((void**)&cA,  g_cA);
    cudaGetSymbolAddress((void**)&cH,  g_cH);
    cudaGetSymbolAddress((void**)&cIn, g_cIn);

    cudaFuncSetAttribute(gemm_f16,
                         cudaFuncAttributeMaxDynamicSharedMemorySize, GEMM_SMEM);

    const size_t WSZ = (size_t)Dd * Dd;

    // Prep: x -> half; weights -> half, k-pair interleaved [K/2][N]
    {
        int n4x = (int)((size_t)BT * Dd / 4);
        f2h_kernel<<<n4x / 256, 256>>>(x, xh, n4x);
        dim3 wg(Dd / 4 / 256, Dd / 2);   // (2, 1024)
        wint_kernel<<<wg, 256>>>(Wi, wh + 0 * WSZ);
        wint_kernel<<<wg, 256>>>(Wf, wh + 1 * WSZ);
        wint_kernel<<<wg, 256>>>(Wg, wh + 2 * WSZ);
        wint_kernel<<<wg, 256>>>(Wo, wh + 3 * WSZ);
    }

    dim3 ggrid(Dd / BN, BT / BM);   // (16, 128)
    dim3 gblk(256);

    // i: silu(i); f: sigmoid(f); g: silu(g)
    gemm_f16<<<ggrid, gblk, GEMM_SMEM>>>(xh, wh + 0 * WSZ, siA, BT, Dd, Dd, 2);
    gemm_f16<<<ggrid, gblk, GEMM_SMEM>>>(xh, wh + 1 * WSZ, aA,  BT, Dd, Dd, 1);
    gemm_f16<<<ggrid, gblk, GEMM_SMEM>>>(xh, wh + 2 * WSZ, gg,  BT, Dd, Dd, 2);

    const int scanBlocks = Bb * NC * (Dd / 256);   // 1024
    scan_pass1<<<scanBlocks, 256>>>(aA, siA, o, cA, cH);
    scan_pass2<<<(Bb * Dd) / 256, 256>>>(cA, cH, cIn);
    scan_pass3<<<scanBlocks, 256>>>(aA, cIn, o);

    norm_gate_kernel<<<BT, 256>>>(o, gg, gw, uh);

    // Output GEMM (identity epilogue)
    gemm_f16<<<ggrid, gblk, GEMM_SMEM>>>(uh, wh + 3 * WSZ, out, BT, Dd, Dd, 0);
}

// round 13
// speedup vs baseline: 2.0720x; 1.0378x over previous
#include <cuda_runtime.h>
#include <cuda_fp16.h>
#include <math.h>
#include <stdint.h>

// Problem shape (fixed for this dataset instance)
constexpr int Bb = 4;
constexpr int Tt = 4096;
constexpr int Dd = 2048;
constexpr int BT = Bb * Tt;           // 16384 rows
constexpr float EPS = 1e-5f;

// Scan chunking
constexpr int NC = 32;
constexpr int CH = Tt / NC;           // 128

// GEMM tiling (mma.sync f16 m16n8k16 + ldmatrix): CTA 128x128, BK=32, 4 stages
constexpr int BM = 128;
constexpr int BN = 128;
constexpr int BK = 32;
constexpr int LDA_H = 40;             // A row: 32 data halves + 8 pad (80 B)
constexpr int LDB_H = 136;            // B row: 128 data halves + 8 pad (272 B)
constexpr int STAGES = 4;
constexpr int A_BYTES = BM * LDA_H * 2;               // 10240
constexpr int B_BYTES = BK * LDB_H * 2;               // 8704
constexpr int STG_BYTES = A_BYTES + B_BYTES;          // 18944
constexpr int GEMM_SMEM = STAGES * STG_BYTES;         // 75776

// Scratch (device globals — no allocation allowed)
__device__ float  g_a   [(size_t)BT * Dd];     // sigmoid(f)
__device__ float  g_si  [(size_t)BT * Dd];     // silu(i)
__device__ float  g_gg  [(size_t)BT * Dd];     // silu(g)
__device__ float  g_o   [(size_t)BT * Dd];     // local (per-chunk) scan result
__device__ __half g_uh  [(size_t)BT * Dd];     // fp16 u (input to output GEMM)
__device__ __half g_xh  [(size_t)BT * Dd];     // fp16 x
__device__ __half g_wh  [(size_t)4 * Dd * Dd]; // fp16 weights, native [K][N]
__device__ float  g_cA  [(size_t)Bb * NC * Dd];
__device__ float  g_cH  [(size_t)Bb * NC * Dd];
__device__ float  g_cIn [(size_t)Bb * NC * Dd];

// ---------------------------------------------------------------------------
__device__ __forceinline__ void cp16(uint32_t dst, const void* src) {
    asm volatile("cp.async.cg.shared.global [%0], [%1], 16;\n" :: "r"(dst), "l"(src));
}

__device__ __forceinline__ void mma16816(float* d, const uint32_t* a, const uint32_t* b) {
    asm volatile(
        "mma.sync.aligned.m16n8k16.row.col.f32.f16.f16.f32 "
        "{%0,%1,%2,%3}, {%4,%5,%6,%7}, {%8,%9}, {%0,%1,%2,%3};"
        : "+f"(d[0]), "+f"(d[1]), "+f"(d[2]), "+f"(d[3])
        : "r"(a[0]), "r"(a[1]), "r"(a[2]), "r"(a[3]), "r"(b[0]), "r"(b[1]));
}

__device__ __forceinline__ void ldsm_x4(uint32_t& r0, uint32_t& r1,
                                        uint32_t& r2, uint32_t& r3, uint32_t addr) {
    asm volatile("ldmatrix.sync.aligned.m8n8.x4.shared.b16 {%0,%1,%2,%3}, [%4];"
                 : "=r"(r0), "=r"(r1), "=r"(r2), "=r"(r3) : "r"(addr));
}

__device__ __forceinline__ void ldsm_x4_t(uint32_t& r0, uint32_t& r1,
                                          uint32_t& r2, uint32_t& r3, uint32_t addr) {
    asm volatile("ldmatrix.sync.aligned.m8n8.x4.trans.shared.b16 {%0,%1,%2,%3}, [%4];"
                 : "=r"(r0), "=r"(r1), "=r"(r2), "=r"(r3) : "r"(addr));
}

__device__ __forceinline__ float sigm(float v) { return 1.0f / (1.0f + __expf(-v)); }

// ---------------------------------------------------------------------------
// float -> half, contiguous (used for x and all weights)
__global__ void f2h_kernel(const float* __restrict__ in,
                           __half* __restrict__ out, int n4)
{
    int i = blockIdx.x * blockDim.x + threadIdx.x;
    if (i < n4) {
        float4 v = reinterpret_cast<const float4*>(in)[i];
        __half2 h0 = __floats2half2_rn(v.x, v.y);
        __half2 h1 = __floats2half2_rn(v.z, v.w);
        uint2 p;
        p.x = *reinterpret_cast<uint32_t*>(&h0);
        p.y = *reinterpret_cast<uint32_t*>(&h1);
        reinterpret_cast<uint2*>(out)[i] = p;
    }
}

// ---------------------------------------------------------------------------
// C[M,N] = act(A[M,K] * B[K,N]); A half row-major K-contig; B half row-major
// N-contig ([K][N], native). mode: 0 = identity, 1 = sigmoid, 2 = silu.
// 4-stage cp.async, load-after-compute, ldmatrix fragments, 2 CTAs/SM.
// ---------------------------------------------------------------------------
__global__ __launch_bounds__(256, 2)
void gemm_f16(const __half* __restrict__ A, const __half* __restrict__ Bh,
              float* __restrict__ C, int M, int N, int K, int mode)
{
    extern __shared__ char smem[];

    const int tid  = threadIdx.x;
    const int warp = tid >> 5;
    const int lane = tid & 31;
    const int wm   = warp >> 2;          // 0..1
    const int wn   = warp & 3;           // 0..3
    const int gid  = lane >> 2;          // 0..7
    const int tig  = lane & 3;           // 0..3
    const int m0   = blockIdx.y * BM;
    const int n0   = blockIdx.x * BN;

    // ldmatrix lane-address selectors (same for A and B)
    const int lrow = ((lane >> 3) & 1) * 8 + (lane & 7);   // row within 16
    const int lcol = ((lane >> 4) & 1) * 8;                // half-col offset

    float acc[4][4][4];
#pragma unroll
    for (int i = 0; i < 4; i++)
#pragma unroll
        for (int j = 0; j < 4; j++)
#pragma unroll
            for (int r = 0; r < 4; r++)
                acc[i][j][r] = 0.0f;

    const uint32_t smem_b = (uint32_t)__cvta_generic_to_shared(smem);

    auto load_stage = [&](int kt, int s) {
        const int k0 = kt * BK;
        const uint32_t sa = smem_b + s * STG_BYTES;
        const uint32_t sb = sa + A_BYTES;
        // A: 128 rows x 4 chunks of 16B (8 halves) -> 512, 2/thread
#pragma unroll
        for (int i = 0; i < 2; i++) {
            int e = tid + i * 256;
            int r = e >> 2, c = e & 3;
            cp16(sa + r * (LDA_H * 2) + c * 16,
                 A + (size_t)(m0 + r) * K + k0 + c * 8);
        }
        // B: 32 rows x 16 chunks of 16B -> 512, 2/thread
#pragma unroll
        for (int i = 0; i < 2; i++) {
            int e = tid + i * 256;
            int r = e >> 4, c = e & 15;
            cp16(sb + r * (LDB_H * 2) + c * 16,
                 Bh + (size_t)(k0 + r) * N + n0 + c * 8);
        }
        asm volatile("cp.async.commit_group;\n" ::: "memory");
    };

    const int KT = K / BK;               // 64
    load_stage(0, 0);
    load_stage(1, 1);
    load_stage(2, 2);

    for (int kt = 0; kt < KT; kt++) {
        const int s = kt & 3;
        if (kt < KT - 2)
            asm volatile("cp.async.wait_group 2;\n" ::: "memory");
        else if (kt == KT - 2)
            asm volatile("cp.async.wait_group 1;\n" ::: "memory");
        else
            asm volatile("cp.async.wait_group 0;\n" ::: "memory");
        __syncthreads();

        const uint32_t sa = smem_b + s * STG_BYTES;
        const uint32_t sb = sa + A_BYTES;

#pragma unroll
        for (int kk = 0; kk < 2; kk++) {             // two k16 steps
            uint32_t af[4][4];
            uint32_t bf[4][2];
            // A fragments: 4 x ldmatrix.x4 (m0,m1 = rows+0/+8 @k0-7; m2,m3 @k8-15)
#pragma unroll
            for (int im = 0; im < 4; im++) {
                uint32_t addr = sa +
                    ((wm * 64 + im * 16 + lrow) * LDA_H + kk * 16 + lcol) * 2;
                ldsm_x4(af[im][0], af[im][1], af[im][2], af[im][3], addr);
            }
            // B fragments: 2 x ldmatrix.trans.x4, each covers 2 n-tiles
#pragma unroll
            for (int p = 0; p < 2; p++) {
                uint32_t addr = sb +
                    ((kk * 16 + lrow) * LDB_H + wn * 32 + p * 16 + lcol) * 2;
                ldsm_x4_t(bf[2 * p][0], bf[2 * p][1],
                          bf[2 * p + 1][0], bf[2 * p + 1][1], addr);
            }
#pragma unroll
            for (int im = 0; im < 4; im++)
#pragma unroll
                for (int in = 0; in < 4; in++)
                    mma16816(acc[im][in], af[im], bf[in]);
        }

        // Issue next load AFTER compute (proven ordering)
        if (kt + 3 < KT)
            load_stage(kt + 3, (kt + 3) & 3);
    }

    // Epilogue with fused activation
#pragma unroll
    for (int im = 0; im < 4; im++) {
        int row0 = m0 + wm * 64 + im * 16 + gid;
#pragma unroll
        for (int in = 0; in < 4; in++) {
            int col = n0 + wn * 32 + in * 8 + 2 * tig;
#pragma unroll
            for (int h = 0; h < 2; h++) {
                float v0 = acc[im][in][2 * h], v1 = acc[im][in][2 * h + 1];
                if (mode == 1)      { v0 = sigm(v0);  v1 = sigm(v1); }
                else if (mode == 2) { v0 *= sigm(v0); v1 *= sigm(v1); }
                *reinterpret_cast<float2*>(
                    &C[(size_t)(row0 + 8 * h) * N + col]) = make_float2(v0, v1);
            }
        }
    }
}

// ---------------------------------------------------------------------------
// Scan pass 1: local scan per chunk; pass 2: chunk-carry scan
// ---------------------------------------------------------------------------
__global__ void scan_pass1(const float* __restrict__ aA,
                           const float* __restrict__ siA,
                           float* __restrict__ o,
                           float* __restrict__ cA,
                           float* __restrict__ cH)
{
    const int blocksPerBC = Dd / 256;            // 8
    int d  = (blockIdx.x % blocksPerBC) * 256 + threadIdx.x;
    int bc = blockIdx.x / blocksPerBC;
    int b  = bc / NC;
    int c  = bc % NC;
    size_t base = ((size_t)b * Tt + (size_t)c * CH) * Dd + d;

    float h = 0.0f, pa = 1.0f;
#pragma unroll 4
    for (int t = 0; t < CH; t++) {
        size_t idx = base + (size_t)t * Dd;
        float a  = aA[idx];
        float in = siA[idx] * (1.0f - a);
        h  = fmaf(a, h, in);
        pa *= a;
        o[idx] = h;
    }
    cA[(size_t)bc * Dd + d] = pa;
    cH[(size_t)bc * Dd + d] = h;
}

__global__ void scan_pass2(const float* __restrict__ cA,
                           const float* __restrict__ cH,
                           float* __restrict__ cIn)
{
    int ch = blockIdx.x * blockDim.x + threadIdx.x;
    int b  = ch / Dd;
    int d  = ch - b * Dd;
    float H = 0.0f;
#pragma unroll
    for (int c = 0; c < NC; c++) {
        size_t idx = ((size_t)b * NC + c) * Dd + d;
        cIn[idx] = H;
        H = fmaf(cA[idx], H, cH[idx]);
    }
}

// ---------------------------------------------------------------------------
// Fused pass3 + RMSNorm + gate: one block per (b, chunk). 1024 threads, each
// handles 2 channels (float2). o_final = o_local + cIn * cumprod(a); then
// u = half( o_final * rsqrt(mean(o^2)+eps) * w * silu_g ).
// ---------------------------------------------------------------------------
__global__ __launch_bounds__(1024)
void scan_norm_kernel(const float* __restrict__ aA,
                      const float* __restrict__ oL,
                      const float* __restrict__ cIn,
                      const float* __restrict__ gsw,
                      const float* __restrict__ w,
                      __half* __restrict__ u)
{
    const int bc = blockIdx.x;                   // b*NC + c
    const int b  = bc / NC;
    const int c  = bc % NC;
    const int tid  = threadIdx.x;                // 0..1023
    const int lane = tid & 31;
    const int wrp  = tid >> 5;

    const float2* a2 = reinterpret_cast<const float2*>(aA);
    const float2* o2 = reinterpret_cast<const float2*>(oL);
    const float2* g2 = reinterpret_cast<const float2*>(gsw);
    const float2* w2 = reinterpret_cast<const float2*>(w);

    float2 pa = make_float2(0.0f, 0.0f);
    if (c > 0) pa = reinterpret_cast<const float2*>(cIn)[(size_t)bc * 1024 + tid];
    const float2 wv = w2[tid];

    __shared__ float sred[2][33];

    for (int t = 0; t < CH; t++) {
        size_t row = (size_t)b * Tt + (size_t)c * CH + t;
        size_t off = row * 1024 + tid;
        float2 av = a2[off];
        float2 ov = o2[off];
        float2 gv = g2[off];
        pa.x *= av.x; pa.y *= av.y;
        float ox = ov.x + pa.x;
        float oy = ov.y + pa.y;

        float s = ox * ox + oy * oy;
#pragma unroll
        for (int k = 16; k > 0; k >>= 1)
            s += __shfl_xor_sync(0xffffffffu, s, k);
        const int buf = t & 1;
        if (lane == 0) sred[buf][wrp] = s;
        __syncthreads();
        if (tid < 32) {
            float v = sred[buf][tid];
#pragma unroll
            for (int k = 16; k > 0; k >>= 1)
                v += __shfl_xor_sync(0xffffffffu, v, k);
            if (tid == 0) sred[buf][32] = v;
        }
        __syncthreads();
        float r = rsqrtf(sred[buf][32] * (1.0f / Dd) + EPS);

        __half2 h = __floats2half2_rn(ox * r * wv.x * gv.x,
                                      oy * r * wv.y * gv.y);
        reinterpret_cast<uint32_t*>(u)[off] = *reinterpret_cast<uint32_t*>(&h);
    }
}

// ---------------------------------------------------------------------------
extern "C" void kernel_launch(void* const* d_in, const int* in_sizes, int n_in,
                              void* d_out, int out_size)
{
    const float* x  = (const float*)d_in[0];
    const float* Wi = (const float*)d_in[1];
    const float* Wf = (const float*)d_in[2];
    const float* Wg = (const float*)d_in[3];
    const float* Wo = (const float*)d_in[4];
    const float* gw = (const float*)d_in[5];
    float* out = (float*)d_out;

    float *aA, *siA, *gg, *o, *cA, *cH, *cIn;
    __half *uh, *xh, *wh;
    cudaGetSymbolAddress((void**)&aA,  g_a);
    cudaGetSymbolAddress((void**)&siA, g_si);
    cudaGetSymbolAddress((void**)&gg,  g_gg);
    cudaGetSymbolAddress((void**)&o,   g_o);
    cudaGetSymbolAddress((void**)&uh,  g_uh);
    cudaGetSymbolAddress((void**)&xh,  g_xh);
    cudaGetSymbolAddress((void**)&wh,  g_wh);
    cudaGetSymbolAddress((void**)&cA,  g_cA);
    cudaGetSymbolAddress((void**)&cH,  g_cH);
    cudaGetSymbolAddress((void**)&cIn, g_cIn);

    cudaFuncSetAttribute(gemm_f16,
                         cudaFuncAttributeMaxDynamicSharedMemorySize, GEMM_SMEM);

    const size_t WSZ = (size_t)Dd * Dd;

    // Prep: x and weights -> half (weights stay native [K][N])
    {
        int n4x = (int)((size_t)BT * Dd / 4);
        int n4w = (int)(WSZ / 4);
        f2h_kernel<<<n4x / 256, 256>>>(x,  xh, n4x);
        f2h_kernel<<<n4w / 256, 256>>>(Wi, wh + 0 * WSZ, n4w);
        f2h_kernel<<<n4w / 256, 256>>>(Wf, wh + 1 * WSZ, n4w);
        f2h_kernel<<<n4w / 256, 256>>>(Wg, wh + 2 * WSZ, n4w);
        f2h_kernel<<<n4w / 256, 256>>>(Wo, wh + 3 * WSZ, n4w);
    }

    dim3 ggrid(Dd / BN, BT / BM);   // (16, 128)
    dim3 gblk(256);

    // i: silu(i); f: sigmoid(f); g: silu(g)
    gemm_f16<<<ggrid, gblk, GEMM_SMEM>>>(xh, wh + 0 * WSZ, siA, BT, Dd, Dd, 2);
    gemm_f16<<<ggrid, gblk, GEMM_SMEM>>>(xh, wh + 1 * WSZ, aA,  BT, Dd, Dd, 1);
    gemm_f16<<<ggrid, gblk, GEMM_SMEM>>>(xh, wh + 2 * WSZ, gg,  BT, Dd, Dd, 2);

    const int scanBlocks = Bb * NC * (Dd / 256);   // 1024
    scan_pass1<<<scanBlocks, 256>>>(aA, siA, o, cA, cH);
    scan_pass2<<<(Bb * Dd) / 256, 256>>>(cA, cH, cIn);

    // Fused fixup + RMSNorm + gate
    scan_norm_kernel<<<Bb * NC, 1024>>>(aA, o, cIn, gg, gw, uh);

    // Output GEMM (identity epilogue)
    gemm_f16<<<ggrid, gblk, GEMM_SMEM>>>(uh, wh + 3 * WSZ, out, BT, Dd, Dd, 0);
}

// round 14
// speedup vs baseline: 2.1926x; 1.0582x over previous
#include <cuda_runtime.h>
#include <cuda_fp16.h>
#include <math.h>
#include <stdint.h>

// Problem shape (fixed for this dataset instance)
constexpr int Bb = 4;
constexpr int Tt = 4096;
constexpr int Dd = 2048;
constexpr int BT = Bb * Tt;           // 16384 rows
constexpr float EPS = 1e-5f;

// Scan chunking
constexpr int NC = 64;
constexpr int CH = Tt / NC;           // 64
constexpr int D2 = Dd / 2;            // 1024 half2 channels

// GEMM tiling (mma.sync f16 m16n8k16 + ldmatrix): CTA 128x128, BK=32, 4 stages
constexpr int BM = 128;
constexpr int BN = 128;
constexpr int BK = 32;
constexpr int LDA_H = 40;             // A row: 32 data halves + 8 pad (80 B)
constexpr int LDB_H = 136;            // B row: 128 data halves + 8 pad (272 B)
constexpr int A_BYTES = BM * LDA_H * 2;               // 10240
constexpr int B_BYTES = BK * LDB_H * 2;               // 8704
constexpr int STG_BYTES = A_BYTES + B_BYTES;          // 18944
constexpr int GEMM_SMEM = 4 * STG_BYTES;              // 75776

// Scratch (device globals — no allocation allowed)
__device__ __half g_a   [(size_t)BT * Dd];     // sigmoid(f)
__device__ __half g_si  [(size_t)BT * Dd];     // silu(i)
__device__ __half g_gg  [(size_t)BT * Dd];     // silu(g)
__device__ __half g_o   [(size_t)BT * Dd];     // local (per-chunk) scan result
__device__ __half g_uh  [(size_t)BT * Dd];     // fp16 u (input to output GEMM)
__device__ __half g_xh  [(size_t)BT * Dd];     // fp16 x
__device__ __half g_wh  [(size_t)4 * Dd * Dd]; // fp16 weights, native [K][N]
__device__ float  g_cA  [(size_t)Bb * NC * Dd];
__device__ float  g_cH  [(size_t)Bb * NC * Dd];
__device__ float  g_cIn [(size_t)Bb * NC * Dd];

// ---------------------------------------------------------------------------
__device__ __forceinline__ void cp16(uint32_t dst, const void* src) {
    asm volatile("cp.async.cg.shared.global [%0], [%1], 16;\n" :: "r"(dst), "l"(src));
}

__device__ __forceinline__ void mma16816(float* d, const uint32_t* a, const uint32_t* b) {
    asm volatile(
        "mma.sync.aligned.m16n8k16.row.col.f32.f16.f16.f32 "
        "{%0,%1,%2,%3}, {%4,%5,%6,%7}, {%8,%9}, {%0,%1,%2,%3};"
        : "+f"(d[0]), "+f"(d[1]), "+f"(d[2]), "+f"(d[3])
        : "r"(a[0]), "r"(a[1]), "r"(a[2]), "r"(a[3]), "r"(b[0]), "r"(b[1]));
}

__device__ __forceinline__ void ldsm_x4(uint32_t& r0, uint32_t& r1,
                                        uint32_t& r2, uint32_t& r3, uint32_t addr) {
    asm volatile("ldmatrix.sync.aligned.m8n8.x4.shared.b16 {%0,%1,%2,%3}, [%4];"
                 : "=r"(r0), "=r"(r1), "=r"(r2), "=r"(r3) : "r"(addr));
}

__device__ __forceinline__ void ldsm_x4_t(uint32_t& r0, uint32_t& r1,
                                          uint32_t& r2, uint32_t& r3, uint32_t addr) {
    asm volatile("ldmatrix.sync.aligned.m8n8.x4.trans.shared.b16 {%0,%1,%2,%3}, [%4];"
                 : "=r"(r0), "=r"(r1), "=r"(r2), "=r"(r3) : "r"(addr));
}

__device__ __forceinline__ float sigm(float v) { return 1.0f / (1.0f + __expf(-v)); }

// ---------------------------------------------------------------------------
// float -> half, contiguous (x)
__global__ void f2h_kernel(const float* __restrict__ in,
                           __half* __restrict__ out, int n4)
{
    int i = blockIdx.x * blockDim.x + threadIdx.x;
    if (i < n4) {
        float4 v = reinterpret_cast<const float4*>(in)[i];
        __half2 h0 = __floats2half2_rn(v.x, v.y);
        __half2 h1 = __floats2half2_rn(v.z, v.w);
        uint2 p;
        p.x = *reinterpret_cast<uint32_t*>(&h0);
        p.y = *reinterpret_cast<uint32_t*>(&h1);
        reinterpret_cast<uint2*>(out)[i] = p;
    }
}

// Batched weight conversion: blockIdx.y selects the weight matrix
__global__ void f2h_w_kernel(const float* __restrict__ W0, const float* __restrict__ W1,
                             const float* __restrict__ W2, const float* __restrict__ W3,
                             __half* __restrict__ out)
{
    const size_t WSZ = (size_t)Dd * Dd;
    const float* in = (blockIdx.y == 0) ? W0 : (blockIdx.y == 1) ? W1
                    : (blockIdx.y == 2) ? W2 : W3;
    int i = blockIdx.x * blockDim.x + threadIdx.x;
    float4 v = reinterpret_cast<const float4*>(in)[i];
    __half2 h0 = __floats2half2_rn(v.x, v.y);
    __half2 h1 = __floats2half2_rn(v.z, v.w);
    uint2 p;
    p.x = *reinterpret_cast<uint32_t*>(&h0);
    p.y = *reinterpret_cast<uint32_t*>(&h1);
    reinterpret_cast<uint2*>(out + blockIdx.y * WSZ)[i] = p;
}

// ---------------------------------------------------------------------------
// C = act(A[M,K] * B[K,N]); A half [M,K], B half [K,N] native.
// mode: 0 = identity (float C), 1 = sigmoid (half C), 2 = silu (half C).
// 4-stage cp.async, load-after-compute, ldmatrix fragments, 2 CTAs/SM.
// ---------------------------------------------------------------------------
__global__ __launch_bounds__(256, 2)
void gemm_f16(const __half* __restrict__ A, const __half* __restrict__ Bh,
              void* __restrict__ Cout, int M, int N, int K, int mode)
{
    extern __shared__ char smem[];

    const int tid  = threadIdx.x;
    const int warp = tid >> 5;
    const int lane = tid & 31;
    const int wm   = warp >> 2;          // 0..1
    const int wn   = warp & 3;           // 0..3
    const int gid  = lane >> 2;          // 0..7
    const int tig  = lane & 3;           // 0..3
    const int m0   = blockIdx.y * BM;
    const int n0   = blockIdx.x * BN;

    const int lrow = ((lane >> 3) & 1) * 8 + (lane & 7);
    const int lcol = ((lane >> 4) & 1) * 8;

    float acc[4][4][4];
#pragma unroll
    for (int i = 0; i < 4; i++)
#pragma unroll
        for (int j = 0; j < 4; j++)
#pragma unroll
            for (int r = 0; r < 4; r++)
                acc[i][j][r] = 0.0f;

    const uint32_t smem_b = (uint32_t)__cvta_generic_to_shared(smem);

    auto load_stage = [&](int kt, int s) {
        const int k0 = kt * BK;
        const uint32_t sa = smem_b + s * STG_BYTES;
        const uint32_t sb = sa + A_BYTES;
#pragma unroll
        for (int i = 0; i < 2; i++) {
            int e = tid + i * 256;
            int r = e >> 2, c = e & 3;
            cp16(sa + r * (LDA_H * 2) + c * 16,
                 A + (size_t)(m0 + r) * K + k0 + c * 8);
        }
#pragma unroll
        for (int i = 0; i < 2; i++) {
            int e = tid + i * 256;
            int r = e >> 4, c = e & 15;
            cp16(sb + r * (LDB_H * 2) + c * 16,
                 Bh + (size_t)(k0 + r) * N + n0 + c * 8);
        }
        asm volatile("cp.async.commit_group;\n" ::: "memory");
    };

    const int KT = K / BK;               // 64
    load_stage(0, 0);
    load_stage(1, 1);
    load_stage(2, 2);

    for (int kt = 0; kt < KT; kt++) {
        const int s = kt & 3;
        if (kt < KT - 2)
            asm volatile("cp.async.wait_group 2;\n" ::: "memory");
        else if (kt == KT - 2)
            asm volatile("cp.async.wait_group 1;\n" ::: "memory");
        else
            asm volatile("cp.async.wait_group 0;\n" ::: "memory");
        __syncthreads();

        const uint32_t sa = smem_b + s * STG_BYTES;
        const uint32_t sb = sa + A_BYTES;

#pragma unroll
        for (int kk = 0; kk < 2; kk++) {
            uint32_t af[4][4];
            uint32_t bf[4][2];
#pragma unroll
            for (int im = 0; im < 4; im++) {
                uint32_t addr = sa +
                    ((wm * 64 + im * 16 + lrow) * LDA_H + kk * 16 + lcol) * 2;
                ldsm_x4(af[im][0], af[im][1], af[im][2], af[im][3], addr);
            }
#pragma unroll
            for (int p = 0; p < 2; p++) {
                uint32_t addr = sb +
                    ((kk * 16 + lrow) * LDB_H + wn * 32 + p * 16 + lcol) * 2;
                ldsm_x4_t(bf[2 * p][0], bf[2 * p][1],
                          bf[2 * p + 1][0], bf[2 * p + 1][1], addr);
            }
#pragma unroll
            for (int im = 0; im < 4; im++)
#pragma unroll
                for (int in = 0; in < 4; in++)
                    mma16816(acc[im][in], af[im], bf[in]);
        }

        if (kt + 3 < KT)
            load_stage(kt + 3, (kt + 3) & 3);
    }

    // Epilogue: fused activation; half stores for gate modes, float for mode 0
#pragma unroll
    for (int im = 0; im < 4; im++) {
        int row0 = m0 + wm * 64 + im * 16 + gid;
#pragma unroll
        for (int in = 0; in < 4; in++) {
            int col = n0 + wn * 32 + in * 8 + 2 * tig;
#pragma unroll
            for (int h = 0; h < 2; h++) {
                size_t off = (size_t)(row0 + 8 * h) * N + col;
                float v0 = acc[im][in][2 * h], v1 = acc[im][in][2 * h + 1];
                if (mode == 0) {
                    *reinterpret_cast<float2*>(
                        reinterpret_cast<float*>(Cout) + off) = make_float2(v0, v1);
                } else {
                    if (mode == 1) { v0 = sigm(v0);  v1 = sigm(v1); }
                    else           { v0 *= sigm(v0); v1 *= sigm(v1); }
                    __half2 hv = __floats2half2_rn(v0, v1);
                    *reinterpret_cast<uint32_t*>(
                        reinterpret_cast<__half*>(Cout) + off) =
                        *reinterpret_cast<uint32_t*>(&hv);
                }
            }
        }
    }
}

// ---------------------------------------------------------------------------
// Scan pass 1: local scan per chunk (2 channels/thread via half2)
// ---------------------------------------------------------------------------
__global__ void scan_pass1(const __half2* __restrict__ aA,
                           const __half2* __restrict__ siA,
                           __half2* __restrict__ o,
                           float2* __restrict__ cA,
                           float2* __restrict__ cH)
{
    const int blocksPerBC = D2 / 256;            // 4
    int d  = (blockIdx.x % blocksPerBC) * 256 + threadIdx.x;   // 0..1023
    int bc = blockIdx.x / blocksPerBC;
    int b  = bc / NC;
    int c  = bc % NC;
    size_t base = ((size_t)b * Tt + (size_t)c * CH) * D2 + d;

    float2 h  = make_float2(0.0f, 0.0f);
    float2 pa = make_float2(1.0f, 1.0f);
#pragma unroll 4
    for (int t = 0; t < CH; t++) {
        size_t idx = base + (size_t)t * D2;
        float2 a  = __half22float2(aA[idx]);
        float2 si = __half22float2(siA[idx]);
        h.x = fmaf(a.x, h.x, si.x * (1.0f - a.x));
        h.y = fmaf(a.y, h.y, si.y * (1.0f - a.y));
        pa.x *= a.x; pa.y *= a.y;
        o[idx] = __floats2half2_rn(h.x, h.y);
    }
    cA[(size_t)bc * D2 + d] = pa;
    cH[(size_t)bc * D2 + d] = h;
}

// Pass 2: sequential scan over NC chunk carries (tiny)
__global__ void scan_pass2(const float2* __restrict__ cA,
                           const float2* __restrict__ cH,
                           float2* __restrict__ cIn)
{
    int ch = blockIdx.x * blockDim.x + threadIdx.x;  // 0..Bb*D2-1
    int b  = ch / D2;
    int d  = ch - b * D2;
    float2 H = make_float2(0.0f, 0.0f);
#pragma unroll
    for (int c = 0; c < NC; c++) {
        size_t idx = ((size_t)b * NC + c) * D2 + d;
        cIn[idx] = H;
        float2 av = cA[idx], hv = cH[idx];
        H.x = fmaf(av.x, H.x, hv.x);
        H.y = fmaf(av.y, H.y, hv.y);
    }
}

// ---------------------------------------------------------------------------
// Fused fixup + RMSNorm + gate: one block per (b, chunk), 1024 thr x 2 ch.
// ---------------------------------------------------------------------------
__global__ __launch_bounds__(1024)
void scan_norm_kernel(const __half2* __restrict__ aA,
                      const __half2* __restrict__ oL,
                      const float2* __restrict__ cIn,
                      const __half2* __restrict__ gsw,
                      const float* __restrict__ w,
                      __half* __restrict__ u)
{
    const int bc = blockIdx.x;                   // b*NC + c
    const int b  = bc / NC;
    const int c  = bc % NC;
    const int tid  = threadIdx.x;                // 0..1023
    const int lane = tid & 31;
    const int wrp  = tid >> 5;

    float2 pa = make_float2(0.0f, 0.0f);
    if (c > 0) pa = cIn[(size_t)bc * D2 + tid];
    const float2 wv = reinterpret_cast<const float2*>(w)[tid];

    __shared__ float sred[2][33];

    for (int t = 0; t < CH; t++) {
        size_t row = (size_t)b * Tt + (size_t)c * CH + t;
        size_t off = row * D2 + tid;
        float2 av = __half22float2(aA[off]);
        float2 ov = __half22float2(oL[off]);
        float2 gv = __half22float2(gsw[off]);
        pa.x *= av.x; pa.y *= av.y;
        float ox = ov.x + pa.x;
        float oy = ov.y + pa.y;

        float s = ox * ox + oy * oy;
#pragma unroll
        for (int k = 16; k > 0; k >>= 1)
            s += __shfl_xor_sync(0xffffffffu, s, k);
        const int buf = t & 1;
        if (lane == 0) sred[buf][wrp] = s;
        __syncthreads();
        if (tid < 32) {
            float v = sred[buf][tid];
#pragma unroll
            for (int k = 16; k > 0; k >>= 1)
                v += __shfl_xor_sync(0xffffffffu, v, k);
            if (tid == 0) sred[buf][32] = v;
        }
        __syncthreads();
        float r = rsqrtf(sred[buf][32] * (1.0f / Dd) + EPS);

        __half2 h = __floats2half2_rn(ox * r * wv.x * gv.x,
                                      oy * r * wv.y * gv.y);
        reinterpret_cast<uint32_t*>(u)[off] = *reinterpret_cast<uint32_t*>(&h);
    }
}

// ---------------------------------------------------------------------------
extern "C" void kernel_launch(void* const* d_in, const int* in_sizes, int n_in,
                              void* d_out, int out_size)
{
    const float* x  = (const float*)d_in[0];
    const float* Wi = (const float*)d_in[1];
    const float* Wf = (const float*)d_in[2];
    const float* Wg = (const float*)d_in[3];
    const float* Wo = (const float*)d_in[4];
    const float* gw = (const float*)d_in[5];
    float* out = (float*)d_out;

    __half *aA, *siA, *gg, *o, *uh, *xh, *wh;
    float *cA, *cH, *cIn;
    cudaGetSymbolAddress((void**)&aA,  g_a);
    cudaGetSymbolAddress((void**)&siA, g_si);
    cudaGetSymbolAddress((void**)&gg,  g_gg);
    cudaGetSymbolAddress((void**)&o,   g_o);
    cudaGetSymbolAddress((void**)&uh,  g_uh);
    cudaGetSymbolAddress((void**)&xh,  g_xh);
    cudaGetSymbolAddress((void**)&wh,  g_wh);
    cudaGetSymbolAddress((void**)&cA,  g_cA);
    cudaGetSymbolAddress((void**)&cH,  g_cH);
    cudaGetSymbolAddress((void**)&cIn, g_cIn);

    cudaFuncSetAttribute(gemm_f16,
                         cudaFuncAttributeMaxDynamicSharedMemorySize, GEMM_SMEM);

    const size_t WSZ = (size_t)Dd * Dd;

    // Prep: x -> half; 4 weights in one batched launch
    {
        int n4x = (int)((size_t)BT * Dd / 4);
        f2h_kernel<<<n4x / 256, 256>>>(x, xh, n4x);
        dim3 wg((unsigned)(WSZ / 4 / 256), 4);
        f2h_w_kernel<<<wg, 256>>>(Wi, Wf, Wg, Wo, wh);
    }

    dim3 ggrid(Dd / BN, BT / BM);   // (16, 128)
    dim3 gblk(256);

    // i: silu(i); f: sigmoid(f); g: silu(g) — all fp16 outputs
    gemm_f16<<<ggrid, gblk, GEMM_SMEM>>>(xh, wh + 0 * WSZ, siA, BT, Dd, Dd, 2);
    gemm_f16<<<ggrid, gblk, GEMM_SMEM>>>(xh, wh + 1 * WSZ, aA,  BT, Dd, Dd, 1);
    gemm_f16<<<ggrid, gblk, GEMM_SMEM>>>(xh, wh + 2 * WSZ, gg,  BT, Dd, Dd, 2);

    const int scanBlocks = Bb * NC * (D2 / 256);   // 1024
    scan_pass1<<<scanBlocks, 256>>>(
        reinterpret_cast<const __half2*>(aA),
        reinterpret_cast<const __half2*>(siA),
        reinterpret_cast<__half2*>(o),
        reinterpret_cast<float2*>(cA),
        reinterpret_cast<float2*>(cH));
    scan_pass2<<<(Bb * D2) / 256, 256>>>(
        reinterpret_cast<const float2*>(cA),
        reinterpret_cast<const float2*>(cH),
        reinterpret_cast<float2*>(cIn));

    scan_norm_kernel<<<Bb * NC, 1024>>>(
        reinterpret_cast<const __half2*>(aA),
        reinterpret_cast<const __half2*>(o),
        reinterpret_cast<const float2*>(cIn),
        reinterpret_cast<const __half2*>(gg),
        gw, uh);

    // Output GEMM (identity epilogue, float output)
    gemm_f16<<<ggrid, gblk, GEMM_SMEM>>>(uh, wh + 3 * WSZ, out, BT, Dd, Dd, 0);
}